// round 3
// baseline (speedup 1.0000x reference)
#include <cuda_runtime.h>
#include <cstdint>

#define TDIM 2048
#define CB 4
#define HN 12
#define HD 64
#define BH (CB*HN)
#define CEMB 768
#define N3C 2304

// Scratch for q,k,v in (B,H,T,D) layout. 25.2MB each.
__device__ __align__(16) float g_q[(size_t)BH * TDIM * HD];
__device__ __align__(16) float g_k[(size_t)BH * TDIM * HD];
__device__ __align__(16) float g_v[(size_t)BH * TDIM * HD];

// ---------------------------------------------------------------------------
// Kernel 1: QKV GEMM  C[8192,2304] = x[8192,768] @ W[768,2304] + b, fused with
// scatter into q/k/v (B,H,T,D) scratch. 128x128 tile, K-tile 8, 256 threads,
// 8x8 micro-tile per thread.
// ---------------------------------------------------------------------------
__global__ __launch_bounds__(256)
void qkv_gemm_kernel(const float* __restrict__ A,
                     const float* __restrict__ W,
                     const float* __restrict__ bias)
{
    __shared__ __align__(16) float As[8][128];   // [k][m]
    __shared__ __align__(16) float Bs[8][128];   // [k][n]

    const int tid = threadIdx.x;
    const int tx = tid & 15;        // 0..15  -> 8 cols each
    const int ty = tid >> 4;        // 0..15  -> 8 rows each
    const int m0 = blockIdx.y << 7;
    const int n0 = blockIdx.x << 7;

    // A loader: 128 rows x 8 k, 2 threads per row (float4 each)
    const int la_m = tid >> 1;            // 0..127
    const int la_k = (tid & 1) << 2;      // 0 or 4
    // B loader: 8 k-rows x 128 n, 32 threads per row (float4 each)
    const int lb_k = tid >> 5;            // 0..7
    const int lb_n = (tid & 31) << 2;     // 0..124

    const float* Ap = A + (size_t)(m0 + la_m) * CEMB + la_k;
    const float* Bp = W + (size_t)lb_k * N3C + n0 + lb_n;

    float acc[8][8];
    #pragma unroll
    for (int i = 0; i < 8; i++)
        #pragma unroll
        for (int j = 0; j < 8; j++)
            acc[i][j] = 0.0f;

    for (int k0 = 0; k0 < CEMB; k0 += 8) {
        const float4 a4 = *(const float4*)(Ap + k0);
        const float4 b4 = *(const float4*)(Bp + (size_t)k0 * N3C);
        __syncthreads();
        As[la_k + 0][la_m] = a4.x;
        As[la_k + 1][la_m] = a4.y;
        As[la_k + 2][la_m] = a4.z;
        As[la_k + 3][la_m] = a4.w;
        *(float4*)&Bs[lb_k][lb_n] = b4;
        __syncthreads();

        #pragma unroll
        for (int kk = 0; kk < 8; kk++) {
            const float4 a0 = *(const float4*)&As[kk][ty << 3];
            const float4 a1 = *(const float4*)&As[kk][(ty << 3) + 4];
            const float4 b0 = *(const float4*)&Bs[kk][tx << 3];
            const float4 b1 = *(const float4*)&Bs[kk][(tx << 3) + 4];
            const float ar[8] = {a0.x, a0.y, a0.z, a0.w, a1.x, a1.y, a1.z, a1.w};
            const float br[8] = {b0.x, b0.y, b0.z, b0.w, b1.x, b1.y, b1.z, b1.w};
            #pragma unroll
            for (int i = 0; i < 8; i++)
                #pragma unroll
                for (int j = 0; j < 8; j++)
                    acc[i][j] = fmaf(ar[i], br[j], acc[i][j]);
        }
    }

    // Epilogue: bias + scatter to q/k/v (B,H,T,D).
    // Tile (128 cols) never straddles a q/k/v section (768 = 6*128), and an
    // aligned 8-col group never straddles a head (64) boundary.
    #pragma unroll
    for (int jg = 0; jg < 2; jg++) {
        const int n = n0 + (tx << 3) + (jg << 2);
        const int sec = n / CEMB;
        const int nn = n - sec * CEMB;
        const int hh = nn >> 6;
        const int d  = nn & 63;
        float* dst = (sec == 0) ? g_q : (sec == 1) ? g_k : g_v;
        const float4 bv = *(const float4*)(bias + n);
        #pragma unroll
        for (int i = 0; i < 8; i++) {
            const int m = m0 + (ty << 3) + i;
            const int b = m >> 11;           // /2048
            const int t = m & 2047;
            float4 o;
            o.x = acc[i][jg * 4 + 0] + bv.x;
            o.y = acc[i][jg * 4 + 1] + bv.y;
            o.z = acc[i][jg * 4 + 2] + bv.z;
            o.w = acc[i][jg * 4 + 3] + bv.w;
            *(float4*)&dst[(((size_t)(b * HN + hh)) * TDIM + t) * HD + d] = o;
        }
    }
}

// ---------------------------------------------------------------------------
// Kernel 2: causal ReLU attention, Y = relu(scale*Q*K^T masked) @ V.
// One block per (bh, q-tile of 64). 256 threads (16x16), 4x4 micro-tiles.
// Q and K held transposed in smem with XOR swizzle (bits [4:2] of d XORed
// into the 4-col group index) -> conflict-free float4 LDS and only 2-way
// transpose-STS. S^T is written (swizzled, float4) into the K buffer.
// Static smem: 3 * 64*64 * 4B = 48KB.
// ---------------------------------------------------------------------------
__global__ __launch_bounds__(256)
void attn_kernel(float* __restrict__ out)
{
    __shared__ __align__(16) float Qt[64 * 64];   // Qt[d][r^...]
    __shared__ __align__(16) float KS[64 * 64];   // Kt[d][c^...] then St[c][r^...]
    __shared__ __align__(16) float Vs[64 * 64];   // Vs[c][d] plain

    const int tid = threadIdx.x;
    const int tx = tid & 15;     // 0..15 -> cols (keys / D-out), 4 each
    const int ty = tid >> 4;     // 0..15 -> rows (queries), 4 each
    const int bh = blockIdx.y;
    const int b = bh / HN;
    const int h = bh - b * HN;
    const int itile = 31 - blockIdx.x;   // heavy (long-causal) tiles first

    const float* Qg = g_q + ((size_t)bh * TDIM + itile * 64) * HD;
    const float* Kg = g_k + (size_t)bh * TDIM * HD;
    const float* Vg = g_v + (size_t)bh * TDIM * HD;

    // Load Q tile transposed + swizzled: Qt[d*64 + (r ^ (d&28))]
    #pragma unroll
    for (int p = 0; p < 4; p++) {
        const int e = p * 1024 + tid * 4;
        const int r = e >> 6;
        const int d0 = e & 63;             // multiple of 4
        const int sw = d0 & 28;            // same for d0..d0+3
        const float4 v = *(const float4*)(Qg + e);
        Qt[(d0 + 0) * 64 + (r ^ sw)] = v.x;
        Qt[(d0 + 1) * 64 + (r ^ sw)] = v.y;
        Qt[(d0 + 2) * 64 + (r ^ sw)] = v.z;
        Qt[(d0 + 3) * 64 + (r ^ sw)] = v.w;
    }

    float yacc[4][4];
    #pragma unroll
    for (int i = 0; i < 4; i++)
        #pragma unroll
        for (int j = 0; j < 4; j++)
            yacc[i][j] = 0.0f;

    const float scale = 0.125f;   // 1/sqrt(64)

    for (int j = 0; j <= itile; j++) {
        __syncthreads();   // prev iter's reads of KS(St)/Vs done; Qt ready (1st iter)
        // Load K tile transposed+swizzled, V tile plain
        #pragma unroll
        for (int p = 0; p < 4; p++) {
            const int e = p * 1024 + tid * 4;
            const int c = e >> 6;
            const int d0 = e & 63;
            const int sw = d0 & 28;
            const float4 kv = *(const float4*)(Kg + j * 64 * HD + e);
            KS[(d0 + 0) * 64 + (c ^ sw)] = kv.x;
            KS[(d0 + 1) * 64 + (c ^ sw)] = kv.y;
            KS[(d0 + 2) * 64 + (c ^ sw)] = kv.z;
            KS[(d0 + 3) * 64 + (c ^ sw)] = kv.w;
            *(float4*)&Vs[e] = *(const float4*)(Vg + j * 64 * HD + e);
        }
        __syncthreads();

        // GEMM1: S[r][c] = sum_d Q[r][d]*K[c][d]
        float s[4][4];
        #pragma unroll
        for (int i = 0; i < 4; i++)
            #pragma unroll
            for (int jj = 0; jj < 4; jj++)
                s[i][jj] = 0.0f;

        #pragma unroll 8
        for (int d = 0; d < 64; d++) {
            const int sw = d & 28;
            const float4 qv = *(const float4*)&Qt[(d << 6) + ((ty << 2) ^ sw)];
            const float4 kv = *(const float4*)&KS[(d << 6) + ((tx << 2) ^ sw)];
            const float qr[4] = {qv.x, qv.y, qv.z, qv.w};
            const float kr[4] = {kv.x, kv.y, kv.z, kv.w};
            #pragma unroll
            for (int i = 0; i < 4; i++)
                #pragma unroll
                for (int jj = 0; jj < 4; jj++)
                    s[i][jj] = fmaf(qr[i], kr[jj], s[i][jj]);
        }

        // scale + relu (+ causal mask only on the diagonal tile)
        #pragma unroll
        for (int i = 0; i < 4; i++)
            #pragma unroll
            for (int jj = 0; jj < 4; jj++)
                s[i][jj] = fmaxf(s[i][jj] * scale, 0.0f);
        if (j == itile) {
            #pragma unroll
            for (int i = 0; i < 4; i++)
                #pragma unroll
                for (int jj = 0; jj < 4; jj++)
                    if (((tx << 2) + jj) > ((ty << 2) + i)) s[i][jj] = 0.0f;
        }

        __syncthreads();   // all GEMM1 reads of KS done before overwrite
        // Store S^T swizzled into KS: St[c*64 + (r ^ (c&28))], float4 over r
        #pragma unroll
        for (int jj = 0; jj < 4; jj++) {
            const int c = (tx << 2) + jj;
            const float4 sv = make_float4(s[0][jj], s[1][jj], s[2][jj], s[3][jj]);
            *(float4*)&KS[(c << 6) + ((ty << 2) ^ (c & 28))] = sv;
        }
        __syncthreads();

        // GEMM2: Y[r][d] += sum_c S[r][c] * V[c][d]
        #pragma unroll 8
        for (int c = 0; c < 64; c++) {
            const float4 sv = *(const float4*)&KS[(c << 6) + ((ty << 2) ^ (c & 28))];
            const float4 vv = *(const float4*)&Vs[(c << 6) + (tx << 2)];
            const float sr[4] = {sv.x, sv.y, sv.z, sv.w};
            const float vr[4] = {vv.x, vv.y, vv.z, vv.w};
            #pragma unroll
            for (int i = 0; i < 4; i++)
                #pragma unroll
                for (int jj = 0; jj < 4; jj++)
                    yacc[i][jj] = fmaf(sr[i], vr[jj], yacc[i][jj]);
        }
    }

    // Epilogue: out[b][t][h*64+d]
    const int tbase = itile * 64 + (ty << 2);
    #pragma unroll
    for (int i = 0; i < 4; i++) {
        const int t = tbase + i;
        const float4 o = make_float4(yacc[i][0], yacc[i][1], yacc[i][2], yacc[i][3]);
        *(float4*)&out[((size_t)(b * TDIM + t)) * CEMB + h * HD + (tx << 2)] = o;
    }
}

// ---------------------------------------------------------------------------
extern "C" void kernel_launch(void* const* d_in, const int* in_sizes, int n_in,
                              void* d_out, int out_size)
{
    const float* x    = (const float*)d_in[0];   // (4,2048,768)
    const float* w    = (const float*)d_in[1];   // (768,2304)
    const float* bias = (const float*)d_in[2];   // (2304,)
    float* out = (float*)d_out;                  // (4,2048,768)

    dim3 g1(N3C / 128, (CB * TDIM) / 128);       // (18, 64)
    qkv_gemm_kernel<<<g1, 256>>>(x, w, bias);

    dim3 g2(TDIM / 64, BH);                      // (32, 48)
    attn_kernel<<<g2, 256>>>(out);
}

// round 4
// speedup vs baseline: 1.0809x; 1.0809x over previous
#include <cuda_runtime.h>
#include <cstdint>

#define TDIM 2048
#define CB 4
#define HN 12
#define HD 64
#define BH (CB*HN)
#define CEMB 768
#define N3C 2304

// Scratch for q,k,v in (B,H,T,D) layout.
__device__ __align__(16) float g_q[(size_t)BH * TDIM * HD];
__device__ __align__(16) float g_k[(size_t)BH * TDIM * HD];
__device__ __align__(16) float g_v[(size_t)BH * TDIM * HD];

// ---------------------------------------------------------------------------
// Kernel 1: QKV GEMM  C[8192,2304] = x[8192,768] @ W[768,2304] + b, fused with
// scatter into q/k/v (B,H,T,D) scratch. 128x128 tile, K-tile 8, 256 threads,
// 8x8 micro-tile. Double-buffered smem: ONE sync per k-iteration, gmem loads
// for tile i+1 overlap compute of tile i.
// ---------------------------------------------------------------------------
__global__ __launch_bounds__(256)
void qkv_gemm_kernel(const float* __restrict__ A,
                     const float* __restrict__ W,
                     const float* __restrict__ bias)
{
    __shared__ __align__(16) float As[2][8][128];   // [buf][k][m]
    __shared__ __align__(16) float Bs[2][8][128];   // [buf][k][n]

    const int tid = threadIdx.x;
    const int tx = tid & 15;        // 8 cols each
    const int ty = tid >> 4;        // 8 rows each
    const int m0 = blockIdx.y << 7;
    const int n0 = blockIdx.x << 7;

    const int la_m = tid >> 1;            // 0..127
    const int la_k = (tid & 1) << 2;      // 0 or 4
    const int lb_k = tid >> 5;            // 0..7
    const int lb_n = (tid & 31) << 2;     // 0..124

    const float* Ap = A + (size_t)(m0 + la_m) * CEMB + la_k;
    const float* Bp = W + (size_t)lb_k * N3C + n0 + lb_n;

    float acc[8][8];
    #pragma unroll
    for (int i = 0; i < 8; i++)
        #pragma unroll
        for (int j = 0; j < 8; j++)
            acc[i][j] = 0.0f;

    // Prologue: tile 0 into buffer 0
    {
        const float4 a4 = *(const float4*)(Ap);
        const float4 b4 = *(const float4*)(Bp);
        As[0][la_k + 0][la_m] = a4.x;
        As[0][la_k + 1][la_m] = a4.y;
        As[0][la_k + 2][la_m] = a4.z;
        As[0][la_k + 3][la_m] = a4.w;
        *(float4*)&Bs[0][lb_k][lb_n] = b4;
    }
    __syncthreads();

    int buf = 0;
    for (int k0 = 0; k0 < CEMB; k0 += 8) {
        const bool has_next = (k0 + 8) < CEMB;
        float4 a_next, b_next;
        if (has_next) {
            a_next = *(const float4*)(Ap + k0 + 8);
            b_next = *(const float4*)(Bp + (size_t)(k0 + 8) * N3C);
        }

        #pragma unroll
        for (int kk = 0; kk < 8; kk++) {
            const float4 a0 = *(const float4*)&As[buf][kk][ty << 3];
            const float4 a1 = *(const float4*)&As[buf][kk][(ty << 3) + 4];
            const float4 b0 = *(const float4*)&Bs[buf][kk][tx << 3];
            const float4 b1 = *(const float4*)&Bs[buf][kk][(tx << 3) + 4];
            const float ar[8] = {a0.x, a0.y, a0.z, a0.w, a1.x, a1.y, a1.z, a1.w};
            const float br[8] = {b0.x, b0.y, b0.z, b0.w, b1.x, b1.y, b1.z, b1.w};
            #pragma unroll
            for (int i = 0; i < 8; i++)
                #pragma unroll
                for (int j = 0; j < 8; j++)
                    acc[i][j] = fmaf(ar[i], br[j], acc[i][j]);
        }

        if (has_next) {
            const int nb = buf ^ 1;
            As[nb][la_k + 0][la_m] = a_next.x;
            As[nb][la_k + 1][la_m] = a_next.y;
            As[nb][la_k + 2][la_m] = a_next.z;
            As[nb][la_k + 3][la_m] = a_next.w;
            *(float4*)&Bs[nb][lb_k][lb_n] = b_next;
            __syncthreads();
            buf = nb;
        }
    }

    // Epilogue: bias + scatter to q/k/v (B,H,T,D).
    #pragma unroll
    for (int jg = 0; jg < 2; jg++) {
        const int n = n0 + (tx << 3) + (jg << 2);
        const int sec = n / CEMB;
        const int nn = n - sec * CEMB;
        const int hh = nn >> 6;
        const int d  = nn & 63;
        float* dst = (sec == 0) ? g_q : (sec == 1) ? g_k : g_v;
        const float4 bv = *(const float4*)(bias + n);
        #pragma unroll
        for (int i = 0; i < 8; i++) {
            const int m = m0 + (ty << 3) + i;
            const int b = m >> 11;
            const int t = m & 2047;
            float4 o;
            o.x = acc[i][jg * 4 + 0] + bv.x;
            o.y = acc[i][jg * 4 + 1] + bv.y;
            o.z = acc[i][jg * 4 + 2] + bv.z;
            o.w = acc[i][jg * 4 + 3] + bv.w;
            *(float4*)&dst[(((size_t)(b * HN + hh)) * TDIM + t) * HD + d] = o;
        }
    }
}

// ---------------------------------------------------------------------------
// Kernel 2: causal ReLU attention, Y = relu(scale*Q*K^T masked) @ V.
// One block per (bh, q-tile of 64). 128 threads: tx 0..15 (4 cols each),
// ty 0..7 (8 rows each) -> 8x4 micro-tile: 32 FFMA per 3 LDS.128.
// Q/K transposed in smem with XOR swizzle; S^T reuses the K buffer.
// K tile prefetched to registers before the barrier; V tile via cp.async.
// Static smem: 3 * 64*64 * 4B = 48KB -> 4 blocks/SM.
// ---------------------------------------------------------------------------
__global__ __launch_bounds__(128)
void attn_kernel(float* __restrict__ out)
{
    __shared__ __align__(16) float Qt[64 * 64];   // Qt[d][r^sw]
    __shared__ __align__(16) float KS[64 * 64];   // Kt[d][c^sw] then St[c][r^sw]
    __shared__ __align__(16) float Vs[64 * 64];   // Vs[c][d] plain

    const int tid = threadIdx.x;
    const int tx = tid & 15;     // cols (keys / D-out), 4 each
    const int ty = tid >> 4;     // 0..7, rows (queries), 8 each
    const int bh = blockIdx.y;
    const int b = bh / HN;
    const int h = bh - b * HN;
    const int itile = 31 - blockIdx.x;   // heavy tiles first

    const float* Qg = g_q + ((size_t)bh * TDIM + itile * 64) * HD;
    const float* Kg = g_k + (size_t)bh * TDIM * HD;
    const float* Vg = g_v + (size_t)bh * TDIM * HD;

    const uint32_t vs_base = (uint32_t)__cvta_generic_to_shared(Vs);

    // Load Q tile transposed + swizzled: Qt[d*64 + (r ^ (d&28))]
    #pragma unroll
    for (int p = 0; p < 8; p++) {
        const int e = p * 512 + tid * 4;
        const int r = e >> 6;
        const int d0 = e & 63;
        const int sw = d0 & 28;
        const float4 v = *(const float4*)(Qg + e);
        Qt[(d0 + 0) * 64 + (r ^ sw)] = v.x;
        Qt[(d0 + 1) * 64 + (r ^ sw)] = v.y;
        Qt[(d0 + 2) * 64 + (r ^ sw)] = v.z;
        Qt[(d0 + 3) * 64 + (r ^ sw)] = v.w;
    }

    float yacc[8][4];
    #pragma unroll
    for (int i = 0; i < 8; i++)
        #pragma unroll
        for (int j = 0; j < 4; j++)
            yacc[i][j] = 0.0f;

    const float scale = 0.125f;   // 1/sqrt(64)
    const int x8 = ty << 3;       // row base for this thread

    for (int j = 0; j <= itile; j++) {
        // Prefetch K tile into registers (overlaps prev GEMM2 + barrier)
        float4 kr[8];
        #pragma unroll
        for (int p = 0; p < 8; p++)
            kr[p] = *(const float4*)(Kg + j * 64 * HD + p * 512 + tid * 4);

        __syncthreads();   // A: prev iter's reads of KS(St)/Vs done (Qt on 1st)

        // V tile: gmem -> smem via cp.async (bypasses registers)
        #pragma unroll
        for (int p = 0; p < 8; p++) {
            const int e = p * 512 + tid * 4;
            asm volatile("cp.async.cg.shared.global [%0], [%1], 16;\n"
                         :: "r"(vs_base + e * 4), "l"(Vg + j * 64 * HD + e));
        }
        asm volatile("cp.async.commit_group;\n");

        // K tile transposed + swizzled from regs
        #pragma unroll
        for (int p = 0; p < 8; p++) {
            const int e = p * 512 + tid * 4;
            const int c = e >> 6;
            const int d0 = e & 63;
            const int sw = d0 & 28;
            KS[(d0 + 0) * 64 + (c ^ sw)] = kr[p].x;
            KS[(d0 + 1) * 64 + (c ^ sw)] = kr[p].y;
            KS[(d0 + 2) * 64 + (c ^ sw)] = kr[p].z;
            KS[(d0 + 3) * 64 + (c ^ sw)] = kr[p].w;
        }
        asm volatile("cp.async.wait_group 0;\n");
        __syncthreads();   // B: K/V tiles ready

        // GEMM1: S[r][c] = sum_d Q[r][d]*K[c][d], 8x4 micro
        float s[8][4];
        #pragma unroll
        for (int i = 0; i < 8; i++)
            #pragma unroll
            for (int jj = 0; jj < 4; jj++)
                s[i][jj] = 0.0f;

        #pragma unroll 8
        for (int d = 0; d < 64; d++) {
            const int sw = d & 28;
            const float4 q0 = *(const float4*)&Qt[(d << 6) + (x8 ^ sw)];
            const float4 q1 = *(const float4*)&Qt[(d << 6) + ((x8 | 4) ^ sw)];
            const float4 kv = *(const float4*)&KS[(d << 6) + ((tx << 2) ^ sw)];
            const float qr[8] = {q0.x, q0.y, q0.z, q0.w, q1.x, q1.y, q1.z, q1.w};
            const float krr[4] = {kv.x, kv.y, kv.z, kv.w};
            #pragma unroll
            for (int i = 0; i < 8; i++)
                #pragma unroll
                for (int jj = 0; jj < 4; jj++)
                    s[i][jj] = fmaf(qr[i], krr[jj], s[i][jj]);
        }

        // scale + relu (+ causal mask on diagonal tile only)
        #pragma unroll
        for (int i = 0; i < 8; i++)
            #pragma unroll
            for (int jj = 0; jj < 4; jj++)
                s[i][jj] = fmaxf(s[i][jj] * scale, 0.0f);
        if (j == itile) {
            #pragma unroll
            for (int i = 0; i < 8; i++)
                #pragma unroll
                for (int jj = 0; jj < 4; jj++)
                    if (((tx << 2) + jj) > (x8 + i)) s[i][jj] = 0.0f;
        }

        __syncthreads();   // C: all GEMM1 reads of KS done before overwrite

        // Store S^T swizzled into KS: St[c*64 + (r ^ (c&28))]
        #pragma unroll
        for (int jj = 0; jj < 4; jj++) {
            const int c = (tx << 2) + jj;
            const int swc = c & 28;
            *(float4*)&KS[(c << 6) + (x8 ^ swc)] =
                make_float4(s[0][jj], s[1][jj], s[2][jj], s[3][jj]);
            *(float4*)&KS[(c << 6) + ((x8 | 4) ^ swc)] =
                make_float4(s[4][jj], s[5][jj], s[6][jj], s[7][jj]);
        }
        __syncthreads();   // D: St ready

        // GEMM2: Y[r][d] += sum_c S[r][c] * V[c][d], 8x4 micro
        #pragma unroll 8
        for (int c = 0; c < 64; c++) {
            const int swc = c & 28;
            const float4 s0 = *(const float4*)&KS[(c << 6) + (x8 ^ swc)];
            const float4 s1 = *(const float4*)&KS[(c << 6) + ((x8 | 4) ^ swc)];
            const float4 vv = *(const float4*)&Vs[(c << 6) + (tx << 2)];
            const float sr[8] = {s0.x, s0.y, s0.z, s0.w, s1.x, s1.y, s1.z, s1.w};
            const float vr[4] = {vv.x, vv.y, vv.z, vv.w};
            #pragma unroll
            for (int i = 0; i < 8; i++)
                #pragma unroll
                for (int jj = 0; jj < 4; jj++)
                    yacc[i][jj] = fmaf(sr[i], vr[jj], yacc[i][jj]);
        }
    }

    // Epilogue: out[b][t][h*64+d]
    const int tbase = itile * 64 + x8;
    #pragma unroll
    for (int i = 0; i < 8; i++) {
        const int t = tbase + i;
        *(float4*)&out[((size_t)(b * TDIM + t)) * CEMB + h * HD + (tx << 2)] =
            make_float4(yacc[i][0], yacc[i][1], yacc[i][2], yacc[i][3]);
    }
}

// ---------------------------------------------------------------------------
extern "C" void kernel_launch(void* const* d_in, const int* in_sizes, int n_in,
                              void* d_out, int out_size)
{
    const float* x    = (const float*)d_in[0];   // (4,2048,768)
    const float* w    = (const float*)d_in[1];   // (768,2304)
    const float* bias = (const float*)d_in[2];   // (2304,)
    float* out = (float*)d_out;                  // (4,2048,768)

    dim3 g1(N3C / 128, (CB * TDIM) / 128);       // (18, 64)
    qkv_gemm_kernel<<<g1, 256>>>(x, w, bias);

    dim3 g2(TDIM / 64, BH);                      // (32, 48)
    attn_kernel<<<g2, 256 / 2>>>(out);
}

// round 8
// speedup vs baseline: 1.6889x; 1.5625x over previous
#include <cuda_runtime.h>
#include <cstdint>

#define TDIM 2048
#define CB 4
#define HN 12
#define HD 64
#define BH (CB*HN)
#define CEMB 768
#define N3C 2304

#define KV_STRIDE 76                       // smem row stride (floats), conflict-free
#define TILE_FLOATS (64 * KV_STRIDE)       // 4864
#define BUF_FLOATS (2 * TILE_FLOATS)       // K + V, one stage
#define SMEM_BYTES (2 * BUF_FLOATS * 4)    // double buffered = 77824

// Scratch for q,k,v in (B,H,T,D) layout, values pre-rounded to tf32.
__device__ __align__(16) float g_q[(size_t)BH * TDIM * HD];
__device__ __align__(16) float g_k[(size_t)BH * TDIM * HD];
__device__ __align__(16) float g_v[(size_t)BH * TDIM * HD];

__device__ __forceinline__ uint32_t f2tf32(float x) {
    uint32_t u;
    asm("cvt.rna.tf32.f32 %0, %1;" : "=r"(u) : "f"(x));
    return u;
}

__device__ __forceinline__ void mma_tf32(float& d0, float& d1, float& d2, float& d3,
                                         uint32_t a0, uint32_t a1, uint32_t a2, uint32_t a3,
                                         uint32_t b0, uint32_t b1) {
    asm volatile("mma.sync.aligned.m16n8k8.row.col.f32.tf32.tf32.f32 "
                 "{%0,%1,%2,%3}, {%4,%5,%6,%7}, {%8,%9}, {%0,%1,%2,%3};"
                 : "+f"(d0), "+f"(d1), "+f"(d2), "+f"(d3)
                 : "r"(a0), "r"(a1), "r"(a2), "r"(a3), "r"(b0), "r"(b1));
}

__device__ __forceinline__ void cpa16(uint32_t dst, const float* src) {
    asm volatile("cp.async.cg.shared.global [%0], [%1], 16;" :: "r"(dst), "l"(src));
}

// ---------------------------------------------------------------------------
// Kernel 1: QKV GEMM (fp32 FFMA, double-buffered) + bias + tf32 rounding +
// scatter into q/k/v (B,H,T,D).
// ---------------------------------------------------------------------------
__global__ __launch_bounds__(256)
void qkv_gemm_kernel(const float* __restrict__ A,
                     const float* __restrict__ W,
                     const float* __restrict__ bias)
{
    __shared__ __align__(16) float As[2][8][128];
    __shared__ __align__(16) float Bs[2][8][128];

    const int tid = threadIdx.x;
    const int tx = tid & 15;
    const int ty = tid >> 4;
    const int m0 = blockIdx.y << 7;
    const int n0 = blockIdx.x << 7;

    const int la_m = tid >> 1;
    const int la_k = (tid & 1) << 2;
    const int lb_k = tid >> 5;
    const int lb_n = (tid & 31) << 2;

    const float* Ap = A + (size_t)(m0 + la_m) * CEMB + la_k;
    const float* Bp = W + (size_t)lb_k * N3C + n0 + lb_n;

    float acc[8][8];
    #pragma unroll
    for (int i = 0; i < 8; i++)
        #pragma unroll
        for (int j = 0; j < 8; j++)
            acc[i][j] = 0.0f;

    {
        const float4 a4 = *(const float4*)(Ap);
        const float4 b4 = *(const float4*)(Bp);
        As[0][la_k + 0][la_m] = a4.x;
        As[0][la_k + 1][la_m] = a4.y;
        As[0][la_k + 2][la_m] = a4.z;
        As[0][la_k + 3][la_m] = a4.w;
        *(float4*)&Bs[0][lb_k][lb_n] = b4;
    }
    __syncthreads();

    int buf = 0;
    for (int k0 = 0; k0 < CEMB; k0 += 8) {
        const bool has_next = (k0 + 8) < CEMB;
        float4 a_next, b_next;
        if (has_next) {
            a_next = *(const float4*)(Ap + k0 + 8);
            b_next = *(const float4*)(Bp + (size_t)(k0 + 8) * N3C);
        }

        #pragma unroll
        for (int kk = 0; kk < 8; kk++) {
            const float4 a0 = *(const float4*)&As[buf][kk][ty << 3];
            const float4 a1 = *(const float4*)&As[buf][kk][(ty << 3) + 4];
            const float4 b0 = *(const float4*)&Bs[buf][kk][tx << 3];
            const float4 b1 = *(const float4*)&Bs[buf][kk][(tx << 3) + 4];
            const float ar[8] = {a0.x, a0.y, a0.z, a0.w, a1.x, a1.y, a1.z, a1.w};
            const float br[8] = {b0.x, b0.y, b0.z, b0.w, b1.x, b1.y, b1.z, b1.w};
            #pragma unroll
            for (int i = 0; i < 8; i++)
                #pragma unroll
                for (int j = 0; j < 8; j++)
                    acc[i][j] = fmaf(ar[i], br[j], acc[i][j]);
        }

        if (has_next) {
            const int nb = buf ^ 1;
            As[nb][la_k + 0][la_m] = a_next.x;
            As[nb][la_k + 1][la_m] = a_next.y;
            As[nb][la_k + 2][la_m] = a_next.z;
            As[nb][la_k + 3][la_m] = a_next.w;
            *(float4*)&Bs[nb][lb_k][lb_n] = b_next;
            __syncthreads();
            buf = nb;
        }
    }

    // Epilogue: bias + round to tf32 + scatter to q/k/v (B,H,T,D).
    #pragma unroll
    for (int jg = 0; jg < 2; jg++) {
        const int n = n0 + (tx << 3) + (jg << 2);
        const int sec = n / CEMB;
        const int nn = n - sec * CEMB;
        const int hh = nn >> 6;
        const int d  = nn & 63;
        float* dst = (sec == 0) ? g_q : (sec == 1) ? g_k : g_v;
        const float4 bv = *(const float4*)(bias + n);
        #pragma unroll
        for (int i = 0; i < 8; i++) {
            const int m = m0 + (ty << 3) + i;
            const int b = m >> 11;
            const int t = m & 2047;
            float4 o;
            o.x = __uint_as_float(f2tf32(acc[i][jg * 4 + 0] + bv.x));
            o.y = __uint_as_float(f2tf32(acc[i][jg * 4 + 1] + bv.y));
            o.z = __uint_as_float(f2tf32(acc[i][jg * 4 + 2] + bv.z));
            o.w = __uint_as_float(f2tf32(acc[i][jg * 4 + 3] + bv.w));
            *(float4*)&dst[(((size_t)(b * HN + hh)) * TDIM + t) * HD + d] = o;
        }
    }
}

// ---------------------------------------------------------------------------
// Kernel 2: causal ReLU attention on tensor cores (mma.sync m16n8k8 tf32).
// Block = 128 thr / 4 warps; warp w owns S/Y rows 16w..16w+15 of a 64-row
// q-tile. Q fragments register-resident for the whole block. K/V tiles
// double-buffered in smem (row stride 76 -> conflict-free B-fragment loads)
// via cp.async. S stays in registers; accum->A-fragment layout conversion
// done with shfl.sync.
// ---------------------------------------------------------------------------
__global__ __launch_bounds__(128)
void attn_kernel(float* __restrict__ out)
{
    extern __shared__ __align__(16) float smem[];

    const int tid  = threadIdx.x;
    const int w    = tid >> 5;
    const int lane = tid & 31;
    const int p    = lane & 3;        // quad pos
    const int q    = lane >> 2;       // group id (0..7)

    const int bh = blockIdx.y;
    const int b  = bh / HN;
    const int h  = bh - b * HN;
    const int itile = 31 - blockIdx.x;    // heavy tiles first

    const float* Qg = g_q + ((size_t)bh * TDIM + itile * 64) * HD;
    const float* Kg = g_k + (size_t)bh * TDIM * HD;
    const float* Vg = g_v + (size_t)bh * TDIM * HD;

    const uint32_t smem_u = (uint32_t)__cvta_generic_to_shared(smem);

    // ---- Q fragments: 8 k-chunks x 4 regs, loaded once (values already tf32) ----
    uint32_t Qf[8][4];
    {
        const int r0 = (w << 4) + q;
        #pragma unroll
        for (int s = 0; s < 8; s++) {
            const int c0 = (s << 3) + p;
            Qf[s][0] = __float_as_uint(Qg[r0 * 64 + c0]);
            Qf[s][1] = __float_as_uint(Qg[(r0 + 8) * 64 + c0]);
            Qf[s][2] = __float_as_uint(Qg[r0 * 64 + c0 + 4]);
            Qf[s][3] = __float_as_uint(Qg[(r0 + 8) * 64 + c0 + 4]);
        }
    }

    float yacc[8][4];
    #pragma unroll
    for (int g = 0; g < 8; g++)
        #pragma unroll
        for (int r = 0; r < 4; r++)
            yacc[g][r] = 0.0f;

    // ---- pipeline prologue: stage 0 ----
    {
        const uint32_t kd = smem_u;
        const uint32_t vd = smem_u + TILE_FLOATS * 4;
        #pragma unroll
        for (int i = 0; i < 8; i++) {
            const int f = (tid + (i << 7)) << 2;
            const int row = f >> 6, col = f & 63;
            const uint32_t off = (uint32_t)(row * KV_STRIDE + col) << 2;
            cpa16(kd + off, Kg + f);
            cpa16(vd + off, Vg + f);
        }
        asm volatile("cp.async.commit_group;");
    }

    int buf = 0;
    for (int j = 0; j <= itile; j++) {
        if (j < itile) {
            const uint32_t kd = smem_u + (uint32_t)((buf ^ 1) * BUF_FLOATS) * 4;
            const uint32_t vd = kd + TILE_FLOATS * 4;
            const float* Ksrc = Kg + (j + 1) * 4096;
            const float* Vsrc = Vg + (j + 1) * 4096;
            #pragma unroll
            for (int i = 0; i < 8; i++) {
                const int f = (tid + (i << 7)) << 2;
                const int row = f >> 6, col = f & 63;
                const uint32_t off = (uint32_t)(row * KV_STRIDE + col) << 2;
                cpa16(kd + off, Ksrc + f);
                cpa16(vd + off, Vsrc + f);
            }
            asm volatile("cp.async.commit_group;");
            asm volatile("cp.async.wait_group 1;");
        } else {
            asm volatile("cp.async.wait_group 0;");
        }
        __syncthreads();

        const float* Kb = smem + buf * BUF_FLOATS;
        const float* Vb = Kb + TILE_FLOATS;

        // ---- GEMM1: S = Q * K^T ----
        float S[8][4];
        #pragma unroll
        for (int g = 0; g < 8; g++)
            #pragma unroll
            for (int r = 0; r < 4; r++)
                S[g][r] = 0.0f;

        #pragma unroll
        for (int s = 0; s < 8; s++) {
            #pragma unroll
            for (int g = 0; g < 8; g++) {
                const int base = ((g << 3) + q) * KV_STRIDE + (s << 3) + p;
                const uint32_t b0 = __float_as_uint(Kb[base]);
                const uint32_t b1 = __float_as_uint(Kb[base + 4]);
                mma_tf32(S[g][0], S[g][1], S[g][2], S[g][3],
                         Qf[s][0], Qf[s][1], Qf[s][2], Qf[s][3], b0, b1);
            }
        }

        // ---- scale + relu (+ causal mask on diagonal tile), round to tf32 ----
        uint32_t Sb[8][4];
        #pragma unroll
        for (int g = 0; g < 8; g++) {
            float v0 = fmaxf(S[g][0] * 0.125f, 0.0f);
            float v1 = fmaxf(S[g][1] * 0.125f, 0.0f);
            float v2 = fmaxf(S[g][2] * 0.125f, 0.0f);
            float v3 = fmaxf(S[g][3] * 0.125f, 0.0f);
            if (j == itile) {
                const int row0 = (w << 4) + q;
                const int col0 = (g << 3) + (p << 1);
                if (col0     > row0)     v0 = 0.0f;
                if (col0 + 1 > row0)     v1 = 0.0f;
                if (col0     > row0 + 8) v2 = 0.0f;
                if (col0 + 1 > row0 + 8) v3 = 0.0f;
            }
            Sb[g][0] = f2tf32(v0);
            Sb[g][1] = f2tf32(v1);
            Sb[g][2] = f2tf32(v2);
            Sb[g][3] = f2tf32(v3);
        }

        // ---- GEMM2: Y += S * V ----
        const int src0 = (lane & ~3) + (p >> 1);
        const int src2 = src0 + 2;
        const bool odd = (p & 1);
        #pragma unroll
        for (int s = 0; s < 8; s++) {
            // accum layout -> A-fragment layout within the warp
            const uint32_t t00 = __shfl_sync(0xffffffffu, Sb[s][0], src0);
            const uint32_t t01 = __shfl_sync(0xffffffffu, Sb[s][1], src0);
            const uint32_t t20 = __shfl_sync(0xffffffffu, Sb[s][2], src0);
            const uint32_t t21 = __shfl_sync(0xffffffffu, Sb[s][3], src0);
            const uint32_t u00 = __shfl_sync(0xffffffffu, Sb[s][0], src2);
            const uint32_t u01 = __shfl_sync(0xffffffffu, Sb[s][1], src2);
            const uint32_t u20 = __shfl_sync(0xffffffffu, Sb[s][2], src2);
            const uint32_t u21 = __shfl_sync(0xffffffffu, Sb[s][3], src2);
            const uint32_t a0 = odd ? t01 : t00;
            const uint32_t a1 = odd ? t21 : t20;
            const uint32_t a2 = odd ? u01 : u00;
            const uint32_t a3 = odd ? u21 : u20;

            #pragma unroll
            for (int g = 0; g < 8; g++) {
                const int base = ((s << 3) + p) * KV_STRIDE + (g << 3) + q;
                const uint32_t b0 = __float_as_uint(Vb[base]);
                const uint32_t b1 = __float_as_uint(Vb[base + 4 * KV_STRIDE]);
                mma_tf32(yacc[g][0], yacc[g][1], yacc[g][2], yacc[g][3],
                         a0, a1, a2, a3, b0, b1);
            }
        }

        __syncthreads();   // all reads of buf done before it is overwritten
        buf ^= 1;
    }

    // ---- epilogue: out[b][t][h*64+d] ----
    const int t0 = itile * 64 + (w << 4) + q;
    const int d0 = h * 64 + (p << 1);
    #pragma unroll
    for (int g = 0; g < 8; g++) {
        float* o0 = out + ((size_t)(b * TDIM + t0)) * CEMB + d0 + (g << 3);
        float* o1 = out + ((size_t)(b * TDIM + t0 + 8)) * CEMB + d0 + (g << 3);
        o0[0] = yacc[g][0];
        o0[1] = yacc[g][1];
        o1[0] = yacc[g][2];
        o1[1] = yacc[g][3];
    }
}

// ---------------------------------------------------------------------------
extern "C" void kernel_launch(void* const* d_in, const int* in_sizes, int n_in,
                              void* d_out, int out_size)
{
    const float* x    = (const float*)d_in[0];   // (4,2048,768)
    const float* w    = (const float*)d_in[1];   // (768,2304)
    const float* bias = (const float*)d_in[2];   // (2304,)
    float* out = (float*)d_out;                  // (4,2048,768)

    cudaFuncSetAttribute(attn_kernel, cudaFuncAttributeMaxDynamicSharedMemorySize,
                         SMEM_BYTES);

    dim3 g1(N3C / 128, (CB * TDIM) / 128);       // (18, 64)
    qkv_gemm_kernel<<<g1, 256>>>(x, w, bias);

    dim3 g2(TDIM / 64, BH);                      // (32, 48)
    attn_kernel<<<g2, 128, SMEM_BYTES>>>(out);
}

// round 10
// speedup vs baseline: 2.1012x; 1.2441x over previous
#include <cuda_runtime.h>
#include <cstdint>

#define TDIM 2048
#define CB 4
#define HN 12
#define HD 64
#define BH (CB*HN)
#define CEMB 768
#define N3C 2304

// ---- attention smem ----
#define KV_STRIDE 76                       // conflict-free for both B-frag patterns
#define TILE_FLOATS (64 * KV_STRIDE)       // 4864
#define BUF_FLOATS (2 * TILE_FLOATS)       // K + V, one stage
#define ATTN_SMEM (2 * BUF_FLOATS * 4)     // double buffered = 77824 B

// ---- qkv mma smem ----
#define SA 36                              // A tile stride (q*4+p distinct mod 32)
#define SB 136                             // W tile stride (p*8+q distinct mod 32)
#define QKV_STAGE (128*SA + 32*SB)         // 8960 floats per stage
#define QKV_SMEM (2 * QKV_STAGE * 4)       // 71680 B

// Scratch for q,k,v in (B,H,T,D) layout, values tf32-rounded.
__device__ __align__(16) float g_q[(size_t)BH * TDIM * HD];
__device__ __align__(16) float g_k[(size_t)BH * TDIM * HD];
__device__ __align__(16) float g_v[(size_t)BH * TDIM * HD];

__device__ __forceinline__ uint32_t f2tf32(float x) {
    uint32_t u;
    asm("cvt.rna.tf32.f32 %0, %1;" : "=r"(u) : "f"(x));
    return u;
}

__device__ __forceinline__ void mma_tf32(float& d0, float& d1, float& d2, float& d3,
                                         uint32_t a0, uint32_t a1, uint32_t a2, uint32_t a3,
                                         uint32_t b0, uint32_t b1) {
    asm volatile("mma.sync.aligned.m16n8k8.row.col.f32.tf32.tf32.f32 "
                 "{%0,%1,%2,%3}, {%4,%5,%6,%7}, {%8,%9}, {%0,%1,%2,%3};"
                 : "+f"(d0), "+f"(d1), "+f"(d2), "+f"(d3)
                 : "r"(a0), "r"(a1), "r"(a2), "r"(a3), "r"(b0), "r"(b1));
}

__device__ __forceinline__ void cpa16(uint32_t dst, const float* src) {
    asm volatile("cp.async.cg.shared.global [%0], [%1], 16;" :: "r"(dst), "l"(src));
}

// hi/lo 2-way tf32 split: x ~= hi + lo, hi = tf32(x), lo = tf32(x - hi)
__device__ __forceinline__ void tf32_split(float x, uint32_t& hi, uint32_t& lo) {
    hi = f2tf32(x);
    lo = f2tf32(x - __uint_as_float(hi));
}

// ---------------------------------------------------------------------------
// Kernel 1: QKV GEMM on tensor cores with 3xTF32 (2-way split, 3 MMAs:
// hi*hi + hi*lo + lo*hi) -> near-fp32 accuracy. C = x @ W + b, scattered
// into q/k/v (B,H,T,D), tf32-rounded on store.
// 128x128 block tile, K-tile 32, 8 warps each owning 64x32, double-buffered
// cp.async stages.
// ---------------------------------------------------------------------------
__global__ __launch_bounds__(256, 2)
void qkv_mma_kernel(const float* __restrict__ A,
                    const float* __restrict__ W,
                    const float* __restrict__ bias)
{
    extern __shared__ __align__(16) float sm[];

    const int tid  = threadIdx.x;
    const int w    = tid >> 5;
    const int lane = tid & 31;
    const int p    = lane & 3;
    const int q    = lane >> 2;
    const int wm   = w >> 2;          // 0..1  (64-row slab)
    const int wn   = w & 3;           // 0..3  (32-col slab)

    const int m0 = blockIdx.y << 7;
    const int n0 = blockIdx.x << 7;

    const uint32_t smu = (uint32_t)__cvta_generic_to_shared(sm);

    float acc[4][4][4];
    #pragma unroll
    for (int mi = 0; mi < 4; mi++)
        #pragma unroll
        for (int g = 0; g < 4; g++)
            #pragma unroll
            for (int r = 0; r < 4; r++)
                acc[mi][g][r] = 0.0f;

    // prologue: stage 0 (k0 = 0)
    #pragma unroll
    for (int i = 0; i < 4; i++) {
        const int idx = tid + (i << 8);
        const int row = idx >> 3, kq = (idx & 7) << 2;
        const int kr  = idx >> 5, nq = (idx & 31) << 2;
        cpa16(smu + (uint32_t)(row * SA + kq) * 4,
              A + (size_t)(m0 + row) * CEMB + kq);
        cpa16(smu + (uint32_t)(128 * SA + kr * SB + nq) * 4,
              W + (size_t)kr * N3C + n0 + nq);
    }
    asm volatile("cp.async.commit_group;");

    int buf = 0;
    for (int kt = 0; kt < 24; kt++) {
        const int k0 = kt << 5;
        if (kt < 23) {
            const uint32_t sbase = smu + (uint32_t)((buf ^ 1) * QKV_STAGE) * 4;
            #pragma unroll
            for (int i = 0; i < 4; i++) {
                const int idx = tid + (i << 8);
                const int row = idx >> 3, kq = (idx & 7) << 2;
                const int kr  = idx >> 5, nq = (idx & 31) << 2;
                cpa16(sbase + (uint32_t)(row * SA + kq) * 4,
                      A + (size_t)(m0 + row) * CEMB + k0 + 32 + kq);
                cpa16(sbase + (uint32_t)(128 * SA + kr * SB + nq) * 4,
                      W + (size_t)(k0 + 32 + kr) * N3C + n0 + nq);
            }
            asm volatile("cp.async.commit_group;");
            asm volatile("cp.async.wait_group 1;");
        } else {
            asm volatile("cp.async.wait_group 0;");
        }
        __syncthreads();

        const float* As = sm + buf * QKV_STAGE;
        const float* Ws = As + 128 * SA;

        #pragma unroll
        for (int kc = 0; kc < 32; kc += 8) {
            uint32_t ah[4][4], al[4][4], bh[4][2], bl[4][2];
            #pragma unroll
            for (int mi = 0; mi < 4; mi++) {
                const int base = (wm * 64 + mi * 16 + q) * SA + kc + p;
                tf32_split(As[base],              ah[mi][0], al[mi][0]);
                tf32_split(As[base + 8 * SA],     ah[mi][1], al[mi][1]);
                tf32_split(As[base + 4],          ah[mi][2], al[mi][2]);
                tf32_split(As[base + 8 * SA + 4], ah[mi][3], al[mi][3]);
            }
            #pragma unroll
            for (int g = 0; g < 4; g++) {
                const int bb = (kc + p) * SB + wn * 32 + g * 8 + q;
                tf32_split(Ws[bb],          bh[g][0], bl[g][0]);
                tf32_split(Ws[bb + 4 * SB], bh[g][1], bl[g][1]);
            }
            #pragma unroll
            for (int mi = 0; mi < 4; mi++)
                #pragma unroll
                for (int g = 0; g < 4; g++) {
                    // hi*hi + hi*lo + lo*hi  (lo*lo dropped, ~2^-22)
                    mma_tf32(acc[mi][g][0], acc[mi][g][1], acc[mi][g][2], acc[mi][g][3],
                             ah[mi][0], ah[mi][1], ah[mi][2], ah[mi][3],
                             bl[g][0], bl[g][1]);
                    mma_tf32(acc[mi][g][0], acc[mi][g][1], acc[mi][g][2], acc[mi][g][3],
                             al[mi][0], al[mi][1], al[mi][2], al[mi][3],
                             bh[g][0], bh[g][1]);
                    mma_tf32(acc[mi][g][0], acc[mi][g][1], acc[mi][g][2], acc[mi][g][3],
                             ah[mi][0], ah[mi][1], ah[mi][2], ah[mi][3],
                             bh[g][0], bh[g][1]);
                }
        }
        __syncthreads();
        buf ^= 1;
    }

    // Epilogue: bias + tf32 rounding + scatter to q/k/v (B,H,T,D).
    #pragma unroll
    for (int g = 0; g < 4; g++) {
        const int col = n0 + wn * 32 + g * 8 + (p << 1);   // even
        const int sec = col / CEMB;
        const int nn  = col - sec * CEMB;
        const int hh  = nn >> 6;
        const int d   = nn & 63;
        float* dst = (sec == 0) ? g_q : (sec == 1) ? g_k : g_v;
        const float2 bv = *(const float2*)(bias + col);
        #pragma unroll
        for (int mi = 0; mi < 4; mi++) {
            const int row = m0 + wm * 64 + mi * 16 + q;
            #pragma unroll
            for (int half = 0; half < 2; half++) {
                const int rr = row + half * 8;
                const int b = rr >> 11;
                const int t = rr & 2047;
                float2 o;
                o.x = __uint_as_float(f2tf32(acc[mi][g][half * 2 + 0] + bv.x));
                o.y = __uint_as_float(f2tf32(acc[mi][g][half * 2 + 1] + bv.y));
                *(float2*)&dst[(((size_t)(b * HN + hh)) * TDIM + t) * HD + d] = o;
            }
        }
    }
}

// ---------------------------------------------------------------------------
// Kernel 2: causal ReLU attention on tensor cores (mma.sync m16n8k8 tf32).
// q-tile = 128 rows, 8 warps (warp w owns rows 16w..16w+15). Q fragments
// register-resident. 64-row K/V tiles double-buffered via cp.async; each
// tile amortized over 128 query rows. S stays in registers (shfl fix-up).
// ---------------------------------------------------------------------------
__global__ __launch_bounds__(256, 2)
void attn_kernel(float* __restrict__ out)
{
    extern __shared__ __align__(16) float smem[];

    const int tid  = threadIdx.x;
    const int w    = tid >> 5;        // 0..7
    const int lane = tid & 31;
    const int p    = lane & 3;
    const int q    = lane >> 2;

    const int bh = blockIdx.y;
    const int b  = bh / HN;
    const int h  = bh - b * HN;
    const int itile = 15 - blockIdx.x;            // heavy tiles first
    const int jm = 2 * itile + 1;                 // last key tile (inclusive)

    const float* Qg = g_q + ((size_t)bh * TDIM + itile * 128) * HD;
    const float* Kg = g_k + (size_t)bh * TDIM * HD;
    const float* Vg = g_v + (size_t)bh * TDIM * HD;

    const uint32_t smem_u = (uint32_t)__cvta_generic_to_shared(smem);

    // Q fragments: 8 k-chunks x 4 regs (tf32 values already)
    uint32_t Qf[8][4];
    {
        const int r0 = (w << 4) + q;
        #pragma unroll
        for (int s = 0; s < 8; s++) {
            const int c0 = (s << 3) + p;
            Qf[s][0] = __float_as_uint(Qg[r0 * 64 + c0]);
            Qf[s][1] = __float_as_uint(Qg[(r0 + 8) * 64 + c0]);
            Qf[s][2] = __float_as_uint(Qg[r0 * 64 + c0 + 4]);
            Qf[s][3] = __float_as_uint(Qg[(r0 + 8) * 64 + c0 + 4]);
        }
    }

    float yacc[8][4];
    #pragma unroll
    for (int g = 0; g < 8; g++)
        #pragma unroll
        for (int r = 0; r < 4; r++)
            yacc[g][r] = 0.0f;

    // prologue: stage 0 (256 threads -> 4 float4 each per tile)
    {
        const uint32_t kd = smem_u;
        const uint32_t vd = smem_u + TILE_FLOATS * 4;
        #pragma unroll
        for (int i = 0; i < 4; i++) {
            const int f = (tid + (i << 8)) << 2;
            const int row = f >> 6, col = f & 63;
            const uint32_t off = (uint32_t)(row * KV_STRIDE + col) << 2;
            cpa16(kd + off, Kg + f);
            cpa16(vd + off, Vg + f);
        }
        asm volatile("cp.async.commit_group;");
    }

    int buf = 0;
    const int tw = itile * 128 + (w << 4);        // warp's min query row

    for (int j = 0; j <= jm; j++) {
        if (j < jm) {
            const uint32_t kd = smem_u + (uint32_t)((buf ^ 1) * BUF_FLOATS) * 4;
            const uint32_t vd = kd + TILE_FLOATS * 4;
            const float* Ksrc = Kg + (j + 1) * 4096;
            const float* Vsrc = Vg + (j + 1) * 4096;
            #pragma unroll
            for (int i = 0; i < 4; i++) {
                const int f = (tid + (i << 8)) << 2;
                const int row = f >> 6, col = f & 63;
                const uint32_t off = (uint32_t)(row * KV_STRIDE + col) << 2;
                cpa16(kd + off, Ksrc + f);
                cpa16(vd + off, Vsrc + f);
            }
            asm volatile("cp.async.commit_group;");
            asm volatile("cp.async.wait_group 1;");
        } else {
            asm volatile("cp.async.wait_group 0;");
        }
        __syncthreads();

        const float* Kb = smem + buf * BUF_FLOATS;
        const float* Vb = Kb + TILE_FLOATS;

        // GEMM1: S = Q * K^T
        float S[8][4];
        #pragma unroll
        for (int g = 0; g < 8; g++)
            #pragma unroll
            for (int r = 0; r < 4; r++)
                S[g][r] = 0.0f;

        #pragma unroll
        for (int s = 0; s < 8; s++) {
            #pragma unroll
            for (int g = 0; g < 8; g++) {
                const int base = ((g << 3) + q) * KV_STRIDE + (s << 3) + p;
                const uint32_t b0 = __float_as_uint(Kb[base]);
                const uint32_t b1 = __float_as_uint(Kb[base + 4]);
                mma_tf32(S[g][0], S[g][1], S[g][2], S[g][3],
                         Qf[s][0], Qf[s][1], Qf[s][2], Qf[s][3], b0, b1);
            }
        }

        // scale + relu (+ causal mask on diagonal-straddling tiles), tf32 round
        const bool need_mask = ((j << 6) + 63) > tw;   // warp-uniform
        uint32_t Sb[8][4];
        #pragma unroll
        for (int g = 0; g < 8; g++) {
            float v0 = fmaxf(S[g][0] * 0.125f, 0.0f);
            float v1 = fmaxf(S[g][1] * 0.125f, 0.0f);
            float v2 = fmaxf(S[g][2] * 0.125f, 0.0f);
            float v3 = fmaxf(S[g][3] * 0.125f, 0.0f);
            if (need_mask) {
                const int row0 = tw + q;
                const int col0 = (j << 6) + (g << 3) + (p << 1);
                if (col0     > row0)     v0 = 0.0f;
                if (col0 + 1 > row0)     v1 = 0.0f;
                if (col0     > row0 + 8) v2 = 0.0f;
                if (col0 + 1 > row0 + 8) v3 = 0.0f;
            }
            Sb[g][0] = f2tf32(v0);
            Sb[g][1] = f2tf32(v1);
            Sb[g][2] = f2tf32(v2);
            Sb[g][3] = f2tf32(v3);
        }

        // GEMM2: Y += S * V  (accum layout -> A-frag layout via shfl)
        const int src0 = (lane & ~3) + (p >> 1);
        const int src2 = src0 + 2;
        const bool odd = (p & 1);
        #pragma unroll
        for (int s = 0; s < 8; s++) {
            const uint32_t t00 = __shfl_sync(0xffffffffu, Sb[s][0], src0);
            const uint32_t t01 = __shfl_sync(0xffffffffu, Sb[s][1], src0);
            const uint32_t t20 = __shfl_sync(0xffffffffu, Sb[s][2], src0);
            const uint32_t t21 = __shfl_sync(0xffffffffu, Sb[s][3], src0);
            const uint32_t u00 = __shfl_sync(0xffffffffu, Sb[s][0], src2);
            const uint32_t u01 = __shfl_sync(0xffffffffu, Sb[s][1], src2);
            const uint32_t u20 = __shfl_sync(0xffffffffu, Sb[s][2], src2);
            const uint32_t u21 = __shfl_sync(0xffffffffu, Sb[s][3], src2);
            const uint32_t a0 = odd ? t01 : t00;
            const uint32_t a1 = odd ? t21 : t20;
            const uint32_t a2 = odd ? u01 : u00;
            const uint32_t a3 = odd ? u21 : u20;

            #pragma unroll
            for (int g = 0; g < 8; g++) {
                const int base = ((s << 3) + p) * KV_STRIDE + (g << 3) + q;
                const uint32_t b0 = __float_as_uint(Vb[base]);
                const uint32_t b1 = __float_as_uint(Vb[base + 4 * KV_STRIDE]);
                mma_tf32(yacc[g][0], yacc[g][1], yacc[g][2], yacc[g][3],
                         a0, a1, a2, a3, b0, b1);
            }
        }

        __syncthreads();
        buf ^= 1;
    }

    // epilogue: out[b][t][h*64+d]
    const int t0 = itile * 128 + (w << 4) + q;
    const int d0 = h * 64 + (p << 1);
    #pragma unroll
    for (int g = 0; g < 8; g++) {
        float* o0 = out + ((size_t)(b * TDIM + t0)) * CEMB + d0 + (g << 3);
        float* o1 = out + ((size_t)(b * TDIM + t0 + 8)) * CEMB + d0 + (g << 3);
        o0[0] = yacc[g][0];
        o0[1] = yacc[g][1];
        o1[0] = yacc[g][2];
        o1[1] = yacc[g][3];
    }
}

// ---------------------------------------------------------------------------
extern "C" void kernel_launch(void* const* d_in, const int* in_sizes, int n_in,
                              void* d_out, int out_size)
{
    const float* x    = (const float*)d_in[0];   // (4,2048,768)
    const float* w    = (const float*)d_in[1];   // (768,2304)
    const float* bias = (const float*)d_in[2];   // (2304,)
    float* out = (float*)d_out;                  // (4,2048,768)

    cudaFuncSetAttribute(qkv_mma_kernel, cudaFuncAttributeMaxDynamicSharedMemorySize,
                         QKV_SMEM);
    cudaFuncSetAttribute(attn_kernel, cudaFuncAttributeMaxDynamicSharedMemorySize,
                         ATTN_SMEM);

    dim3 g1(N3C / 128, (CB * TDIM) / 128);       // (18, 64)
    qkv_mma_kernel<<<g1, 256, QKV_SMEM>>>(x, w, bias);

    dim3 g2(TDIM / 128, BH);                     // (16, 48)
    attn_kernel<<<g2, 256, ATTN_SMEM>>>(out);
}